// round 15
// baseline (speedup 1.0000x reference)
#include <cuda_runtime.h>
#include <cuda_fp16.h>
#include <cstdint>

// ------------------ static scratch ------------------------------------------
__device__ __align__(256) float  g_raw[33554432];          // raw conv out
__device__ __align__(256) __half g_A0[33554432], g_A1[33554432];
__device__ __align__(256) __half g_B0[8388608],  g_B1[8388608];
__device__ __align__(256) __half g_w0[2097152],  g_w1[2097152];   // all-layer arena
__device__ __align__(256) float  g_tok[8388608];
__device__ __align__(256) float  g_bnpS[524288], g_bnpQ[524288];  // [oc][tile<=2048]
__device__ float g_scale[256], g_shift[256];
__device__ int g_eidx[32768], g_list[32768];
__device__ int g_cnt[12], g_off[12], g_fill[12];

__device__ __forceinline__ float lrelu(float v) { return v >= 0.f ? v : 0.2f * v; }

// ------------------ asm helpers ---------------------------------------------
__device__ __forceinline__ uint32_t smem_u32(const void* p) {
    uint32_t a;
    asm("{ .reg .u64 t; cvta.to.shared.u64 t, %1; cvt.u32.u64 %0, t; }" : "=r"(a) : "l"(p));
    return a;
}
__device__ __forceinline__ void cp16(uint32_t dst, const void* src, int srcsize) {
    asm volatile("cp.async.cg.shared.global [%0], [%1], 16, %2;"
                 :: "r"(dst), "l"(src), "r"(srcsize) : "memory");
}
#define CP_COMMIT() asm volatile("cp.async.commit_group;" ::: "memory")
#define CP_WAIT1()  asm volatile("cp.async.wait_group 1;" ::: "memory")
#define CP_WAIT0()  asm volatile("cp.async.wait_group 0;" ::: "memory")

__device__ __forceinline__ void ldsm_x4(uint32_t* r, uint32_t a) {
    asm volatile("ldmatrix.sync.aligned.m8n8.x4.shared.b16 {%0,%1,%2,%3}, [%4];"
                 : "=r"(r[0]), "=r"(r[1]), "=r"(r[2]), "=r"(r[3]) : "r"(a));
}
__device__ __forceinline__ void mma_f16(float* c, const uint32_t* a, const uint32_t* b) {
    asm volatile("mma.sync.aligned.m16n8k16.row.col.f32.f16.f16.f32 "
                 "{%0,%1,%2,%3}, {%4,%5,%6,%7}, {%8,%9}, {%0,%1,%2,%3};"
                 : "+f"(c[0]), "+f"(c[1]), "+f"(c[2]), "+f"(c[3])
                 : "r"(a[0]), "r"(a[1]), "r"(a[2]), "r"(a[3]), "r"(b[0]), "r"(b[1]));
}
__device__ __forceinline__ uint32_t swz(int row, int ck) {
    return (uint32_t)(row * 128 + ((ck ^ (row & 7)) * 16));
}

// ------- conv0+prep fused: 3->64 3x3 s1 p1 + bias + lrelu + split -> NHWC ---
__global__ __launch_bounds__(256) void conv0prep_kernel(
    const float* __restrict__ x, const float* __restrict__ w,
    const float* __restrict__ bias,
    __half* __restrict__ o0, __half* __restrict__ o1)
{
    __shared__ float ws[1792];
    __shared__ float ins[3][3][36];
    int by = blockIdx.x;
    int b = by >> 8, y = by & 255;
    int x0 = blockIdx.y * 32;
    int t = threadIdx.x;
    for (int i = t; i < 1728; i += 256) ws[i] = w[i];
    if (t < 64) ws[1728 + t] = bias[t];
    for (int i = t; i < 306; i += 256) {
        int c = i / 102, rr = i - c * 102;
        int ky = rr / 34, xx = rr - ky * 34;
        int iy = y + ky - 1, ix = x0 + xx - 1;
        float v = 0.f;
        if ((unsigned)iy < 256u && (unsigned)ix < 256u)
            v = x[((b * 3 + c) * 256 + iy) * 256 + ix];
        ins[c][ky][xx] = v;
    }
    __syncthreads();
    int px = t >> 3, og = t & 7;
    float acc[8];
#pragma unroll
    for (int j = 0; j < 8; j++) acc[j] = ws[1728 + og * 8 + j];
#pragma unroll
    for (int c = 0; c < 3; c++)
#pragma unroll
        for (int ky = 0; ky < 3; ky++)
#pragma unroll
            for (int kx = 0; kx < 3; kx++) {
                float iv = ins[c][ky][px + kx];
                int k = c * 9 + ky * 3 + kx;
#pragma unroll
                for (int j = 0; j < 8; j++)
                    acc[j] = fmaf(iv, ws[(og * 8 + j) * 27 + k], acc[j]);
            }
    size_t base = ((size_t)(b * 256 + y) * 256 + x0 + px) * 64 + og * 8;
    __half h0[8], h1[8];
#pragma unroll
    for (int j = 0; j < 8; j++) {
        float v = lrelu(acc[j]);
        h0[j] = __float2half_rn(v);
        h1[j] = __float2half_rn(v - __half2float(h0[j]));
    }
    *(uint4*)(o0 + base) = *(uint4*)h0;
    *(uint4*)(o1 + base) = *(uint4*)h1;
}

// ---- BN finalize ------------------------------------------------------------
__global__ void bnfin_kernel(const float* __restrict__ g, const float* __restrict__ bt,
                             int gx, float inv_n)
{
    int c = blockIdx.x, t = threadIdx.x;
    float s = 0.f, q = 0.f;
    for (int i = t; i < gx; i += 256) {
        s += g_bnpS[(size_t)c * 2048 + i];
        q += g_bnpQ[(size_t)c * 2048 + i];
    }
    __shared__ float ss[256], qq[256];
    ss[t] = s; qq[t] = q; __syncthreads();
    for (int o = 128; o > 0; o >>= 1) {
        if (t < o) { ss[t] += ss[t + o]; qq[t] += qq[t + o]; }
        __syncthreads();
    }
    if (t == 0) {
        float m = ss[0] * inv_n;
        float is = rsqrtf(qq[0] * inv_n - m * m + 1e-5f);
        float sc = g[c] * is;
        g_scale[c] = sc; g_shift[c] = bt[c] - m * sc;
    }
}

// ---- prep: bn+lrelu + NCHW->NHWC + 2-way fp16 split ------------------------
__global__ void prep_kernel(const float* __restrict__ raw,
                            __half* __restrict__ o0, __half* __restrict__ o1,
                            int C, int cShift, int H, int W)
{
    extern __shared__ float sp[];
    int by = blockIdx.x, b = by / H, y = by - b * H;
    int x0 = blockIdx.y * 32, t = threadIdx.x, st = C + 1;
    for (int i = t; i < C * 32; i += 256) {
        int c = i >> 5, x = i & 31;
        float v = raw[((size_t)(b * C + c) * H + y) * W + x0 + x];
        sp[x * st + c] = lrelu(fmaf(v, g_scale[c], g_shift[c]));
    }
    __syncthreads();
    for (int i = t; i < C * 32; i += 256) {
        int x = i >> cShift, c = i & (C - 1);
        float v = sp[x * st + c];
        __half h0 = __float2half_rn(v);
        float r1 = v - __half2float(h0);
        size_t dst = ((size_t)(b * H + y) * W + x0 + x) * C + c;
        o0[dst] = h0; o1[dst] = __float2half_rn(r1);
    }
}
__global__ void prep_tok_kernel(const float* __restrict__ raw, float* __restrict__ tok,
                                int C, int cShift, int H, int W)
{
    extern __shared__ float sp[];
    int by = blockIdx.x, b = by / H, y = by - b * H;
    int x0 = blockIdx.y * 32, t = threadIdx.x, st = C + 1;
    for (int i = t; i < C * 32; i += 256) {
        int c = i >> 5, x = i & 31;
        float v = raw[((size_t)(b * C + c) * H + y) * W + x0 + x];
        sp[x * st + c] = lrelu(fmaf(v, g_scale[c], g_shift[c]));
    }
    __syncthreads();
    for (int i = t; i < C * 32; i += 256) {
        int x = i >> cShift, c = i & (C - 1);
        tok[((size_t)(b * H + y) * W + x0 + x) * C + c] = sp[x * st + c];
    }
}

// ---- wsplit_all: all 6 layers in one launch, + zero router counters --------
__global__ void wsplit_all_kernel(
    const float* __restrict__ w1p, const float* __restrict__ w2p,
    const float* __restrict__ w3p, const float* __restrict__ w4p,
    const float* __restrict__ w5p, const float* __restrict__ w6p)
{
    int idx = blockIdx.x * 256 + threadIdx.x;
    if (idx < 12) g_cnt[idx] = 0;
    const int ends[6] = {65536, 139264, 401408, 696320, 1286144, 1875968};
    if (idx >= 1875968) return;
    int L = 0;
#pragma unroll
    for (int i = 0; i < 6; i++) if (idx >= ends[i]) L = i + 1;
    int start = L == 0 ? 0 : ends[L - 1];
    int li = idx - start;
    const float* wp;
    int Cin, KW;
    switch (L) {
        case 0: wp = w1p; Cin = 64;  KW = 4; break;
        case 1: wp = w2p; Cin = 64;  KW = 3; break;
        case 2: wp = w3p; Cin = 128; KW = 4; break;
        case 3: wp = w4p; Cin = 128; KW = 3; break;
        case 4: wp = w5p; Cin = 256; KW = 3; break;
        default: wp = w6p; Cin = 256; KW = 3; break;
    }
    int K = KW * KW * Cin;
    int oc = li / K, k = li - oc * K;
    int tap = k / Cin, c = k - tap * Cin;
    int ky = tap / KW, kx = tap - ky * KW;
    float v = wp[((oc * Cin + c) * KW + ky) * KW + kx];
    __half h0 = __float2half_rn(v);
    float r1 = v - __half2float(h0);
    g_w0[idx] = h0; g_w1[idx] = __float2half_rn(r1);
}

// ------------------ mma.sync fp16 implicit-GEMM conv ------------------------
// R8 pipeline; warp grid 4M x 2N; ldsm_x4 for BOTH A and B (32 issues/chunk).
// Swizzle computed per-ks from hoisted linear parts (correct + in-plane).
__global__ __launch_bounds__(256, 2) void conv_mma(
    const __half* __restrict__ a0, const __half* __restrict__ a1,
    const __half* __restrict__ w0, const __half* __restrict__ w1,
    float* __restrict__ raw,
    int cinShift, int KW, int stride, int Hin, int Win,
    int hwShift, int wShift, int Cout, int K, int nChunk)
{
    extern __shared__ char smem[];
    constexpr int NBLK = 64;
    constexpr int APLANE = 16384;
    constexpr int BPLANE = NBLK * 128;
    constexpr int SSTR = 2 * APLANE + 2 * BPLANE;

    const uint32_t sb = smem_u32(smem);
    const int t = threadIdx.x, lane = t & 31, wrp = t >> 5;
    const int warpM = wrp >> 1, warpN = wrp & 1;
    const int tileP = blockIdx.x * 128, ocBase = blockIdx.y * NBLK;
    const int bImg = tileP >> hwShift;
    const int pbase = tileP - (bImg << hwShift);
    const int Cin = 1 << cinShift;

    // hoisted staging addresses
    const int arow = t >> 3, ack = t & 7;
    int ry[4], rx[4], abase[4];
    uint32_t asw[4];
#pragma unroll
    for (int j = 0; j < 4; j++) {
        int row = arow + 32 * j;
        int p = tileP + row;
        int b = p >> hwShift, pp = p - (b << hwShift);
        int oy = pp >> wShift, ox = pp - (oy << wShift);
        ry[j] = oy * stride - 1; rx[j] = ox * stride - 1;
        abase[j] = ((b * Hin + ry[j]) * Win + rx[j]) * Cin + ack * 8;
        asw[j] = swz(row, ack);
    }
    int bbase[2]; uint32_t bsw[2];
#pragma unroll
    for (int j = 0; j < 2; j++) {
        int row = arow + 32 * j;
        bbase[j] = (ocBase + row) * K + ack * 8;
        bsw[j] = swz(row, ack);
    }

    // hoisted ldsm address components (linear parts only; XOR applied per ks)
    //  A rows: r = warpM*32 + mf*16 + (lane&15); col bit = lane>>4
    uint32_t arb[2]; int asx[2];
    const int acb = lane >> 4;
#pragma unroll
    for (int mf = 0; mf < 2; mf++) {
        int r = warpM * 32 + mf * 16 + (lane & 15);
        arb[mf] = (uint32_t)(r * 128);
        asx[mf] = r & 7;
    }
    //  B rows (x4, n16k16): g = lane>>3, row = n0 + (g>>1)*8 + (lane&7), cbit = g&1
    uint32_t brb[2]; int bsx[2];
    const int bg = lane >> 3;
    const int bcb = bg & 1;
#pragma unroll
    for (int np = 0; np < 2; np++) {
        int r = warpN * 32 + np * 16 + ((bg >> 1) << 3) + (lane & 7);
        brb[np] = (uint32_t)(r * 128);
        bsx[np] = r & 7;
    }

    float acc[2][4][4];
#pragma unroll
    for (int i = 0; i < 2; i++)
#pragma unroll
        for (int j = 0; j < 4; j++)
#pragma unroll
            for (int k = 0; k < 4; k++) acc[i][j][k] = 0.f;

    auto load_chunk = [&](int ch, int stage) {
        int k0 = ch * 64;
        int tap = k0 >> cinShift, c0 = k0 - (tap << cinShift);
        int ky = tap / KW, kx = tap - ky * KW;
        int delta = (ky * Win + kx) * Cin + c0;
        uint32_t sbase = sb + stage * SSTR;
#pragma unroll
        for (int j = 0; j < 4; j++) {
            int iy = ry[j] + ky, ix = rx[j] + kx;
            bool ok = ((unsigned)iy < (unsigned)Hin) && ((unsigned)ix < (unsigned)Win);
            int off = abase[j] + delta;
            cp16(sbase + asw[j], ok ? (const void*)(a0 + off) : (const void*)a0, ok ? 16 : 0);
            cp16(sbase + APLANE + asw[j], ok ? (const void*)(a1 + off) : (const void*)a1, ok ? 16 : 0);
        }
#pragma unroll
        for (int j = 0; j < 2; j++) {
            int off = bbase[j] + k0;
            cp16(sbase + 2 * APLANE + bsw[j], w0 + off, 16);
            cp16(sbase + 2 * APLANE + BPLANE + bsw[j], w1 + off, 16);
        }
    };

    load_chunk(0, 0);
    CP_COMMIT();

    int stage = 0;
#pragma unroll 1
    for (int ch = 0; ch < nChunk; ch++) {
        if (ch + 1 < nChunk) {
            load_chunk(ch + 1, stage ^ 1);
            CP_COMMIT();
            CP_WAIT1();
        } else {
            CP_WAIT0();
        }
        __syncthreads();

        uint32_t abase_s = sb + stage * SSTR;
        uint32_t bbase_s = abase_s + 2 * APLANE;
#pragma unroll
        for (int ks = 0; ks < 4; ks++) {
            // per-ks swizzled offsets (correct through the XOR)
            uint32_t aoff[2], boff[2];
#pragma unroll
            for (int mf = 0; mf < 2; mf++)
                aoff[mf] = arb[mf] + (uint32_t)((((ks * 2 + acb) ^ asx[mf])) << 4);
#pragma unroll
            for (int np = 0; np < 2; np++)
                boff[np] = brb[np] + (uint32_t)((((ks * 2 + bcb) ^ bsx[np])) << 4);

            uint32_t b0f[2][4];
            ldsm_x4(b0f[0], bbase_s + boff[0]);
            ldsm_x4(b0f[1], bbase_s + boff[1]);
            uint32_t af[2][4];
            ldsm_x4(af[0], abase_s + aoff[0]);
            ldsm_x4(af[1], abase_s + aoff[1]);
            // a0 * b0
#pragma unroll
            for (int mf = 0; mf < 2; mf++)
#pragma unroll
                for (int np = 0; np < 2; np++) {
                    mma_f16(acc[mf][np * 2],     af[mf], &b0f[np][0]);
                    mma_f16(acc[mf][np * 2 + 1], af[mf], &b0f[np][2]);
                }
            // a0 * b1
            {
                uint32_t b1f[2][4];
                ldsm_x4(b1f[0], bbase_s + BPLANE + boff[0]);
                ldsm_x4(b1f[1], bbase_s + BPLANE + boff[1]);
#pragma unroll
                for (int mf = 0; mf < 2; mf++)
#pragma unroll
                    for (int np = 0; np < 2; np++) {
                        mma_f16(acc[mf][np * 2],     af[mf], &b1f[np][0]);
                        mma_f16(acc[mf][np * 2 + 1], af[mf], &b1f[np][2]);
                    }
            }
            // a1 * b0
            ldsm_x4(af[0], abase_s + APLANE + aoff[0]);
            ldsm_x4(af[1], abase_s + APLANE + aoff[1]);
#pragma unroll
            for (int mf = 0; mf < 2; mf++)
#pragma unroll
                for (int np = 0; np < 2; np++) {
                    mma_f16(acc[mf][np * 2],     af[mf], &b0f[np][0]);
                    mma_f16(acc[mf][np * 2 + 1], af[mf], &b0f[np][2]);
                }
        }
        __syncthreads();
        stage ^= 1;
    }

    // ---- BN partials: fixed-order smem reduction, layout [oc][tile] ----
    float* ssum = (float*)smem;            // [64][32]
    float* ssq  = ((float*)smem) + 2048;
    int slot = warpM * 8 + (lane >> 2);    // 0..31
#pragma unroll
    for (int nf = 0; nf < 4; nf++)
#pragma unroll
        for (int col = 0; col < 2; col++) {
            int oc = warpN * 32 + nf * 8 + (lane & 3) * 2 + col;
            float s = 0.f, q = 0.f;
#pragma unroll
            for (int mf = 0; mf < 2; mf++) {
                float v0 = acc[mf][nf][col];
                float v1 = acc[mf][nf][col + 2];
                s += v0 + v1;
                q += v0 * v0 + v1 * v1;
            }
            ssum[oc * 32 + slot] = s;
            ssq[oc * 32 + slot] = q;
        }
    __syncthreads();
    if (t < 64) {
        float s = 0.f, q = 0.f;
#pragma unroll
        for (int i = 0; i < 32; i++) { s += ssum[t * 32 + i]; q += ssq[t * 32 + i]; }
        size_t pi = (size_t)(ocBase + t) * 2048 + blockIdx.x;
        g_bnpS[pi] = s; g_bnpQ[pi] = q;
    }

    // ---- store raw NCHW fp32 ----
    const size_t cs = (size_t)1 << hwShift;
#pragma unroll
    for (int mf = 0; mf < 2; mf++)
#pragma unroll
        for (int nf = 0; nf < 4; nf++) {
            int m0 = warpM * 32 + mf * 16 + (lane >> 2);
            int n0 = warpN * 32 + nf * 8 + (lane & 3) * 2;
            float* base = raw + (((size_t)bImg * Cout + ocBase + n0) << hwShift) + pbase;
            base[m0] = acc[mf][nf][0];
            base[cs + m0] = acc[mf][nf][1];
            base[m0 + 8] = acc[mf][nf][2];
            base[cs + m0 + 8] = acc[mf][nf][3];
        }
}

// ------------------ head: router -> group -> fused body+cls -----------------
__global__ __launch_bounds__(256) void router_kernel(
    const float* __restrict__ tok, const float* __restrict__ wg)
{
    int warp = (blockIdx.x * 256 + threadIdx.x) >> 5;
    int lane = threadIdx.x & 31;
    if (warp >= 32768) return;
    const float* tp = tok + (size_t)warp * 256;
    float l[12];
#pragma unroll
    for (int e = 0; e < 12; e++) l[e] = 0.f;
#pragma unroll
    for (int i = 0; i < 8; i++) {
        int d = lane + 32 * i;
        float tv = tp[d];
        const float* w = wg + d * 12;
#pragma unroll
        for (int e = 0; e < 12; e++) l[e] = fmaf(tv, __ldg(w + e), l[e]);
    }
#pragma unroll
    for (int e = 0; e < 12; e++)
#pragma unroll
        for (int o = 16; o > 0; o >>= 1) l[e] += __shfl_xor_sync(0xffffffffu, l[e], o);
    if (lane == 0) {
        int best = 0; float bv = l[0];
#pragma unroll
        for (int e = 1; e < 12; e++) if (l[e] > bv) { bv = l[e]; best = e; }
        g_eidx[warp] = best;
        atomicAdd(&g_cnt[best], 1);
    }
}
__global__ void offsets_kernel()
{
    if (threadIdx.x == 0) {
        int s = 0;
        for (int e = 0; e < 12; e++) { g_off[e] = s; g_fill[e] = s; s += g_cnt[e]; }
    }
}
__global__ void scatter_kernel()
{
    int tkn = blockIdx.x * 256 + threadIdx.x;
    if (tkn >= 32768) return;
    int slot = atomicAdd(&g_fill[g_eidx[tkn]], 1);
    g_list[slot] = tkn;
}

// fused body GEMM + classifier
__global__ __launch_bounds__(512) void body_cls_kernel(
    const float* __restrict__ tok, const float* __restrict__ bw,
    const float* __restrict__ bb, const float* __restrict__ ow,
    const float* __restrict__ w1, const float* __restrict__ b1,
    const float* __restrict__ w2, const float* __restrict__ b2,
    float* __restrict__ out)
{
    extern __shared__ float dsm[];                 // 128*257 floats
    __shared__ int stok[128];
    float* As = dsm;
    float* Bs = dsm + 1056;
    int e = blockIdx.y;
    int nt = g_cnt[e];
    int m0 = blockIdx.x * 128;
    if (m0 >= nt) return;
    int t = threadIdx.x;
    if (t < 128) {
        int idx = m0 + t;
        stok[t] = g_list[g_off[e] + (idx < nt ? idx : 0)];
    }
    __syncthreads();
    int tx = t & 15, ty = t >> 4;
    float acc[8][8];
#pragma unroll
    for (int i = 0; i < 8; i++)
#pragma unroll
        for (int j = 0; j < 8; j++) acc[i][j] = 0.f;

    for (int k0 = 0; k0 < 256; k0 += 8) {
        for (int i = t; i < 1024; i += 512) {
            int kk = i & 7, m = i >> 3;
            As[kk * 132 + m] = tok[(size_t)stok[m] * 256 + k0 + kk];
        }
        for (int i = t; i < 2048; i += 512) {
            int kk = i >> 8, n = i & 255;
            Bs[kk * 256 + n] = bw[(size_t)(k0 + kk) * 3072 + e * 256 + n];
        }
        __syncthreads();
#pragma unroll
        for (int kk = 0; kk < 8; kk++) {
            float a[8], b[8];
#pragma unroll
            for (int i = 0; i < 8; i++) a[i] = As[kk * 132 + tx * 8 + i];
#pragma unroll
            for (int j = 0; j < 8; j++) b[j] = Bs[kk * 256 + ty * 8 + j];
#pragma unroll
            for (int i = 0; i < 8; i++)
#pragma unroll
                for (int j = 0; j < 8; j++) acc[i][j] = fmaf(a[i], b[j], acc[i][j]);
        }
        __syncthreads();
    }
#pragma unroll
    for (int i = 0; i < 8; i++) {
        int m = tx * 8 + i;
#pragma unroll
        for (int j = 0; j < 8; j++) {
            int n = ty * 8 + j, col = e * 256 + n;
            float v = acc[i][j] + bb[col];
            v = lrelu(v);
            v = lrelu(v * ow[col]);
            dsm[m * 257 + n] = v;
        }
    }
    __syncthreads();

    int wrp = t >> 5, lane = t & 31;
    for (int m = wrp; m < 128; m += 16) {
        if (m0 + m >= nt) continue;
        float h = b1[lane];
        const float* fr = dsm + m * 257;
#pragma unroll 8
        for (int d = 0; d < 256; d++) h = fmaf(fr[d], __ldg(w1 + d * 32 + lane), h);
        h = lrelu(h) * w2[lane];
#pragma unroll
        for (int o = 16; o > 0; o >>= 1) h += __shfl_xor_sync(0xffffffffu, h, o);
        if (lane == 0) out[stok[m]] = h + b2[0];
    }
}

// ------------------ launch --------------------------------------------------
extern "C" void kernel_launch(void* const* d_in, const int* in_sizes, int n_in,
                              void* d_out, int out_size)
{
    const float* x = (const float*)d_in[0];
    const float* c0w = (const float*)d_in[1];  const float* c0b = (const float*)d_in[2];
    const float* c1w = (const float*)d_in[3];  const float* g1 = (const float*)d_in[4];  const float* b1 = (const float*)d_in[5];
    const float* c2w = (const float*)d_in[6];  const float* g2 = (const float*)d_in[7];  const float* b2 = (const float*)d_in[8];
    const float* c3w = (const float*)d_in[9];  const float* g3 = (const float*)d_in[10]; const float* b3 = (const float*)d_in[11];
    const float* c4w = (const float*)d_in[12]; const float* g4 = (const float*)d_in[13]; const float* b4 = (const float*)d_in[14];
    const float* c5w = (const float*)d_in[15]; const float* g5 = (const float*)d_in[16]; const float* b5 = (const float*)d_in[17];
    const float* c6w = (const float*)d_in[18]; const float* g6 = (const float*)d_in[19]; const float* b6 = (const float*)d_in[20];
    const float* wg = (const float*)d_in[21];
    const float* bw = (const float*)d_in[22]; const float* bb = (const float*)d_in[23];
    const float* ow = (const float*)d_in[24];
    const float* cw1 = (const float*)d_in[25]; const float* cb1 = (const float*)d_in[26];
    const float* cw2 = (const float*)d_in[27]; const float* cb2 = (const float*)d_in[28];
    float* out = (float*)d_out;

    float *raw, *tok;
    __half *A0, *A1, *B0, *B1, *w0, *w1;
    cudaGetSymbolAddress((void**)&raw, g_raw);
    cudaGetSymbolAddress((void**)&tok, g_tok);
    cudaGetSymbolAddress((void**)&A0, g_A0); cudaGetSymbolAddress((void**)&A1, g_A1);
    cudaGetSymbolAddress((void**)&B0, g_B0); cudaGetSymbolAddress((void**)&B1, g_B1);
    cudaGetSymbolAddress((void**)&w0, g_w0); cudaGetSymbolAddress((void**)&w1, g_w1);

    const int O1 = 0, O2 = 65536, O3 = 139264, O4 = 401408, O5 = 696320, O6 = 1286144;

    const int SM64 = 2 * (2 * 16384 + 2 * 64 * 128);   // 98304
    cudaFuncSetAttribute(conv_mma, cudaFuncAttributeMaxDynamicSharedMemorySize, SM64);
    const int SMBC = 128 * 257 * 4;                    // 131584
    cudaFuncSetAttribute(body_cls_kernel, cudaFuncAttributeMaxDynamicSharedMemorySize, SMBC);

    wsplit_all_kernel<<<(1875968 + 255) / 256, 256>>>(c1w, c2w, c3w, c4w, c5w, c6w);
    conv0prep_kernel<<<dim3(2048, 8), 256>>>(x, c0w, c0b, A0, A1);

    // conv1: 64->64 4x4 s2
    conv_mma<<<dim3(1024, 1), 256, SM64>>>(A0, A1, w0 + O1, w1 + O1, raw,
        6, 4, 2, 256, 256, 14, 7, 64, 1024, 16);
    bnfin_kernel<<<64, 256>>>(g1, b1, 1024, 1.f / 131072.f);
    prep_kernel<<<dim3(8 * 128, 4), 256, 32 * 65 * 4>>>(raw, B0, B1, 64, 6, 128, 128);

    // conv2: 64->128 3x3 s1
    conv_mma<<<dim3(1024, 2), 256, SM64>>>(B0, B1, w0 + O2, w1 + O2, raw,
        6, 3, 1, 128, 128, 14, 7, 128, 576, 9);
    bnfin_kernel<<<128, 256>>>(g2, b2, 1024, 1.f / 131072.f);
    prep_kernel<<<dim3(8 * 128, 4), 256, 32 * 129 * 4>>>(raw, A0, A1, 128, 7, 128, 128);

    // conv3: 128->128 4x4 s2
    conv_mma<<<dim3(256, 2), 256, SM64>>>(A0, A1, w0 + O3, w1 + O3, raw,
        7, 4, 2, 128, 128, 12, 6, 128, 2048, 32);
    bnfin_kernel<<<128, 256>>>(g3, b3, 256, 1.f / 32768.f);
    prep_kernel<<<dim3(8 * 64, 2), 256, 32 * 129 * 4>>>(raw, B0, B1, 128, 7, 64, 64);

    // conv4: 128->256 3x3 s1
    conv_mma<<<dim3(256, 4), 256, SM64>>>(B0, B1, w0 + O4, w1 + O4, raw,
        7, 3, 1, 64, 64, 12, 6, 256, 1152, 18);
    bnfin_kernel<<<256, 256>>>(g4, b4, 256, 1.f / 32768.f);
    prep_kernel<<<dim3(8 * 64, 2), 256, 32 * 257 * 4>>>(raw, A0, A1, 256, 8, 64, 64);

    // conv5: 256->256 3x3 s1
    conv_mma<<<dim3(256, 4), 256, SM64>>>(A0, A1, w0 + O5, w1 + O5, raw,
        8, 3, 1, 64, 64, 12, 6, 256, 2304, 36);
    bnfin_kernel<<<256, 256>>>(g5, b5, 256, 1.f / 32768.f);
    prep_kernel<<<dim3(8 * 64, 2), 256, 32 * 257 * 4>>>(raw, B0, B1, 256, 8, 64, 64);

    // conv6: 256->256 3x3 s1
    conv_mma<<<dim3(256, 4), 256, SM64>>>(B0, B1, w0 + O6, w1 + O6, raw,
        8, 3, 1, 64, 64, 12, 6, 256, 2304, 36);
    bnfin_kernel<<<256, 256>>>(g6, b6, 256, 1.f / 32768.f);
    prep_tok_kernel<<<dim3(8 * 64, 2), 256, 32 * 257 * 4>>>(raw, tok, 256, 8, 64, 64);

    // head
    router_kernel<<<4096, 256>>>(tok, wg);
    offsets_kernel<<<1, 32>>>();
    scatter_kernel<<<128, 256>>>();
    body_cls_kernel<<<dim3(256, 12), 512, SMBC>>>(tok, bw, bb, ow,
                                                  cw1, cb1, cw2, cb2, out);
}

// round 16
// speedup vs baseline: 1.0215x; 1.0215x over previous
#include <cuda_runtime.h>
#include <cuda_fp16.h>
#include <cstdint>

// ------------------ static scratch ------------------------------------------
__device__ __align__(256) float  g_raw[33554432];          // raw conv out
__device__ __align__(256) __half g_A0[33554432], g_A1[33554432];
__device__ __align__(256) __half g_B0[8388608],  g_B1[8388608];
__device__ __align__(256) __half g_w0[2097152],  g_w1[2097152];   // all-layer arena
__device__ __align__(256) float  g_tok[8388608];
__device__ __align__(256) float  g_bnpS[524288], g_bnpQ[524288];  // [oc][tile<=2048]
__device__ float g_scale[256], g_shift[256];
__device__ int g_eidx[32768], g_list[32768];
__device__ int g_cnt[12], g_off[12], g_fill[12];

__device__ __forceinline__ float lrelu(float v) { return v >= 0.f ? v : 0.2f * v; }

// ------------------ asm helpers ---------------------------------------------
__device__ __forceinline__ uint32_t smem_u32(const void* p) {
    uint32_t a;
    asm("{ .reg .u64 t; cvta.to.shared.u64 t, %1; cvt.u32.u64 %0, t; }" : "=r"(a) : "l"(p));
    return a;
}
__device__ __forceinline__ void cp16(uint32_t dst, const void* src, int srcsize) {
    asm volatile("cp.async.cg.shared.global [%0], [%1], 16, %2;"
                 :: "r"(dst), "l"(src), "r"(srcsize) : "memory");
}
#define CP_COMMIT() asm volatile("cp.async.commit_group;" ::: "memory")
#define CP_WAIT1()  asm volatile("cp.async.wait_group 1;" ::: "memory")
#define CP_WAIT0()  asm volatile("cp.async.wait_group 0;" ::: "memory")

__device__ __forceinline__ void ldsm_x4(uint32_t* r, uint32_t a) {
    asm volatile("ldmatrix.sync.aligned.m8n8.x4.shared.b16 {%0,%1,%2,%3}, [%4];"
                 : "=r"(r[0]), "=r"(r[1]), "=r"(r[2]), "=r"(r[3]) : "r"(a));
}
__device__ __forceinline__ void ldsm_x2(uint32_t* r, uint32_t a) {
    asm volatile("ldmatrix.sync.aligned.m8n8.x2.shared.b16 {%0,%1}, [%2];"
                 : "=r"(r[0]), "=r"(r[1]) : "r"(a));
}
__device__ __forceinline__ void mma_f16(float* c, const uint32_t* a, const uint32_t* b) {
    asm volatile("mma.sync.aligned.m16n8k16.row.col.f32.f16.f16.f32 "
                 "{%0,%1,%2,%3}, {%4,%5,%6,%7}, {%8,%9}, {%0,%1,%2,%3};"
                 : "+f"(c[0]), "+f"(c[1]), "+f"(c[2]), "+f"(c[3])
                 : "r"(a[0]), "r"(a[1]), "r"(a[2]), "r"(a[3]), "r"(b[0]), "r"(b[1]));
}
__device__ __forceinline__ uint32_t swz(int row, int ck) {
    return (uint32_t)(row * 128 + ((ck ^ (row & 7)) * 16));
}

// ------- conv0+prep fused: 3->64 3x3 s1 p1 + bias + lrelu + split -> NHWC ---
__global__ __launch_bounds__(256) void conv0prep_kernel(
    const float* __restrict__ x, const float* __restrict__ w,
    const float* __restrict__ bias,
    __half* __restrict__ o0, __half* __restrict__ o1)
{
    __shared__ float ws[1792];
    __shared__ float ins[3][3][36];
    int by = blockIdx.x;
    int b = by >> 8, y = by & 255;
    int x0 = blockIdx.y * 32;
    int t = threadIdx.x;
    for (int i = t; i < 1728; i += 256) ws[i] = w[i];
    if (t < 64) ws[1728 + t] = bias[t];
    for (int i = t; i < 306; i += 256) {
        int c = i / 102, rr = i - c * 102;
        int ky = rr / 34, xx = rr - ky * 34;
        int iy = y + ky - 1, ix = x0 + xx - 1;
        float v = 0.f;
        if ((unsigned)iy < 256u && (unsigned)ix < 256u)
            v = x[((b * 3 + c) * 256 + iy) * 256 + ix];
        ins[c][ky][xx] = v;
    }
    __syncthreads();
    int px = t >> 3, og = t & 7;
    float acc[8];
#pragma unroll
    for (int j = 0; j < 8; j++) acc[j] = ws[1728 + og * 8 + j];
#pragma unroll
    for (int c = 0; c < 3; c++)
#pragma unroll
        for (int ky = 0; ky < 3; ky++)
#pragma unroll
            for (int kx = 0; kx < 3; kx++) {
                float iv = ins[c][ky][px + kx];
                int k = c * 9 + ky * 3 + kx;
#pragma unroll
                for (int j = 0; j < 8; j++)
                    acc[j] = fmaf(iv, ws[(og * 8 + j) * 27 + k], acc[j]);
            }
    size_t base = ((size_t)(b * 256 + y) * 256 + x0 + px) * 64 + og * 8;
    __half h0[8], h1[8];
#pragma unroll
    for (int j = 0; j < 8; j++) {
        float v = lrelu(acc[j]);
        h0[j] = __float2half_rn(v);
        h1[j] = __float2half_rn(v - __half2float(h0[j]));
    }
    *(uint4*)(o0 + base) = *(uint4*)h0;
    *(uint4*)(o1 + base) = *(uint4*)h1;
}

// ---- BN finalize ------------------------------------------------------------
__global__ void bnfin_kernel(const float* __restrict__ g, const float* __restrict__ bt,
                             int gx, float inv_n)
{
    int c = blockIdx.x, t = threadIdx.x;
    float s = 0.f, q = 0.f;
    for (int i = t; i < gx; i += 256) {
        s += g_bnpS[(size_t)c * 2048 + i];
        q += g_bnpQ[(size_t)c * 2048 + i];
    }
    __shared__ float ss[256], qq[256];
    ss[t] = s; qq[t] = q; __syncthreads();
    for (int o = 128; o > 0; o >>= 1) {
        if (t < o) { ss[t] += ss[t + o]; qq[t] += qq[t + o]; }
        __syncthreads();
    }
    if (t == 0) {
        float m = ss[0] * inv_n;
        float is = rsqrtf(qq[0] * inv_n - m * m + 1e-5f);
        float sc = g[c] * is;
        g_scale[c] = sc; g_shift[c] = bt[c] - m * sc;
    }
}

// ---- prep: bn+lrelu + NCHW->NHWC + 2-way fp16 split ------------------------
__global__ void prep_kernel(const float* __restrict__ raw,
                            __half* __restrict__ o0, __half* __restrict__ o1,
                            int C, int cShift, int H, int W)
{
    extern __shared__ float sp[];
    int by = blockIdx.x, b = by / H, y = by - b * H;
    int x0 = blockIdx.y * 32, t = threadIdx.x, st = C + 1;
    for (int i = t; i < C * 32; i += 256) {
        int c = i >> 5, x = i & 31;
        float v = raw[((size_t)(b * C + c) * H + y) * W + x0 + x];
        sp[x * st + c] = lrelu(fmaf(v, g_scale[c], g_shift[c]));
    }
    __syncthreads();
    for (int i = t; i < C * 32; i += 256) {
        int x = i >> cShift, c = i & (C - 1);
        float v = sp[x * st + c];
        __half h0 = __float2half_rn(v);
        float r1 = v - __half2float(h0);
        size_t dst = ((size_t)(b * H + y) * W + x0 + x) * C + c;
        o0[dst] = h0; o1[dst] = __float2half_rn(r1);
    }
}

// ---- prep_tok + fused router: bn+lrelu -> tok, + per-token argmax ----------
// C=256, 32 tokens per block; 8 warps x 4 tokens each.
__global__ void prep_tok_kernel(const float* __restrict__ raw, float* __restrict__ tok,
                                const float* __restrict__ wg,
                                int C, int cShift, int H, int W)
{
    extern __shared__ float sp[];
    int by = blockIdx.x, b = by / H, y = by - b * H;
    int x0 = blockIdx.y * 32, t = threadIdx.x, st = C + 1;
    for (int i = t; i < C * 32; i += 256) {
        int c = i >> 5, x = i & 31;
        float v = raw[((size_t)(b * C + c) * H + y) * W + x0 + x];
        sp[x * st + c] = lrelu(fmaf(v, g_scale[c], g_shift[c]));
    }
    __syncthreads();
    for (int i = t; i < C * 32; i += 256) {
        int x = i >> cShift, c = i & (C - 1);
        tok[((size_t)(b * H + y) * W + x0 + x) * C + c] = sp[x * st + c];
    }
    // fused router (identical accumulation order to standalone router_kernel)
    int wrp = t >> 5, lane = t & 31;
#pragma unroll
    for (int xi = 0; xi < 4; xi++) {
        int x = wrp * 4 + xi;
        float l[12];
#pragma unroll
        for (int e = 0; e < 12; e++) l[e] = 0.f;
#pragma unroll
        for (int i = 0; i < 8; i++) {
            int d = lane + 32 * i;
            float tv = sp[x * st + d];
            const float* w = wg + d * 12;
#pragma unroll
            for (int e = 0; e < 12; e++) l[e] = fmaf(tv, __ldg(w + e), l[e]);
        }
#pragma unroll
        for (int e = 0; e < 12; e++)
#pragma unroll
            for (int o = 16; o > 0; o >>= 1) l[e] += __shfl_xor_sync(0xffffffffu, l[e], o);
        if (lane == 0) {
            int best = 0; float bv = l[0];
#pragma unroll
            for (int e = 1; e < 12; e++) if (l[e] > bv) { bv = l[e]; best = e; }
            int token = (b * H + y) * W + x0 + x;
            g_eidx[token] = best;
            atomicAdd(&g_cnt[best], 1);
        }
    }
}

// ---- wsplit_all: all 6 layers in one launch, + zero router counters --------
__global__ void wsplit_all_kernel(
    const float* __restrict__ w1p, const float* __restrict__ w2p,
    const float* __restrict__ w3p, const float* __restrict__ w4p,
    const float* __restrict__ w5p, const float* __restrict__ w6p)
{
    int idx = blockIdx.x * 256 + threadIdx.x;
    if (idx < 12) g_cnt[idx] = 0;
    const int ends[6] = {65536, 139264, 401408, 696320, 1286144, 1875968};
    if (idx >= 1875968) return;
    int L = 0;
#pragma unroll
    for (int i = 0; i < 6; i++) if (idx >= ends[i]) L = i + 1;
    int start = L == 0 ? 0 : ends[L - 1];
    int li = idx - start;
    const float* wp;
    int Cin, KW;
    switch (L) {
        case 0: wp = w1p; Cin = 64;  KW = 4; break;
        case 1: wp = w2p; Cin = 64;  KW = 3; break;
        case 2: wp = w3p; Cin = 128; KW = 4; break;
        case 3: wp = w4p; Cin = 128; KW = 3; break;
        case 4: wp = w5p; Cin = 256; KW = 3; break;
        default: wp = w6p; Cin = 256; KW = 3; break;
    }
    int K = KW * KW * Cin;
    int oc = li / K, k = li - oc * K;
    int tap = k / Cin, c = k - tap * Cin;
    int ky = tap / KW, kx = tap - ky * KW;
    float v = wp[((oc * Cin + c) * KW + ky) * KW + kx];
    __half h0 = __float2half_rn(v);
    float r1 = v - __half2float(h0);
    g_w0[idx] = h0; g_w1[idx] = __float2half_rn(r1);
}

// ------------------ mma.sync fp16 implicit-GEMM conv (R8 verbatim) ----------
__global__ __launch_bounds__(256, 2) void conv_mma(
    const __half* __restrict__ a0, const __half* __restrict__ a1,
    const __half* __restrict__ w0, const __half* __restrict__ w1,
    float* __restrict__ raw,
    int cinShift, int KW, int stride, int Hin, int Win,
    int hwShift, int wShift, int Cout, int K, int nChunk)
{
    extern __shared__ char smem[];
    constexpr int NBLK = 64;
    constexpr int APLANE = 16384;
    constexpr int BPLANE = NBLK * 128;
    constexpr int SSTR = 2 * APLANE + 2 * BPLANE;
    constexpr int WN = NBLK / 4, WNF = WN / 8;

    const uint32_t sb = smem_u32(smem);
    const int t = threadIdx.x, lane = t & 31, wrp = t >> 5;
    const int warpM = wrp >> 2, warpN = wrp & 3;
    const int tileP = blockIdx.x * 128, ocBase = blockIdx.y * NBLK;
    const int bImg = tileP >> hwShift;
    const int pbase = tileP - (bImg << hwShift);
    const int Cin = 1 << cinShift;

    const int arow = t >> 3, ack = t & 7;
    int ry[4], rx[4], abase[4];
    uint32_t asw[4];
#pragma unroll
    for (int j = 0; j < 4; j++) {
        int row = arow + 32 * j;
        int p = tileP + row;
        int b = p >> hwShift, pp = p - (b << hwShift);
        int oy = pp >> wShift, ox = pp - (oy << wShift);
        ry[j] = oy * stride - 1; rx[j] = ox * stride - 1;
        abase[j] = ((b * Hin + ry[j]) * Win + rx[j]) * Cin + ack * 8;
        asw[j] = swz(row, ack);
    }
    int bbase[2]; uint32_t bsw[2];
#pragma unroll
    for (int j = 0; j < 2; j++) {
        int row = arow + 32 * j;
        bbase[j] = (ocBase + row) * K + ack * 8;
        bsw[j] = swz(row, ack);
    }

    float acc[4][WNF][4];
#pragma unroll
    for (int i = 0; i < 4; i++)
#pragma unroll
        for (int j = 0; j < WNF; j++)
#pragma unroll
            for (int k = 0; k < 4; k++) acc[i][j][k] = 0.f;

    auto load_chunk = [&](int ch, int stage) {
        int k0 = ch * 64;
        int tap = k0 >> cinShift, c0 = k0 - (tap << cinShift);
        int ky = tap / KW, kx = tap - ky * KW;
        int delta = (ky * Win + kx) * Cin + c0;
        uint32_t sbase = sb + stage * SSTR;
#pragma unroll
        for (int j = 0; j < 4; j++) {
            int iy = ry[j] + ky, ix = rx[j] + kx;
            bool ok = ((unsigned)iy < (unsigned)Hin) && ((unsigned)ix < (unsigned)Win);
            int off = abase[j] + delta;
            cp16(sbase + asw[j], ok ? (const void*)(a0 + off) : (const void*)a0, ok ? 16 : 0);
            cp16(sbase + APLANE + asw[j], ok ? (const void*)(a1 + off) : (const void*)a1, ok ? 16 : 0);
        }
#pragma unroll
        for (int j = 0; j < 2; j++) {
            int off = bbase[j] + k0;
            cp16(sbase + 2 * APLANE + bsw[j], w0 + off, 16);
            cp16(sbase + 2 * APLANE + BPLANE + bsw[j], w1 + off, 16);
        }
    };

    load_chunk(0, 0);
    CP_COMMIT();

    int stage = 0;
#pragma unroll 1
    for (int ch = 0; ch < nChunk; ch++) {
        if (ch + 1 < nChunk) {
            load_chunk(ch + 1, stage ^ 1);
            CP_COMMIT();
            CP_WAIT1();
        } else {
            CP_WAIT0();
        }
        __syncthreads();

        uint32_t abase_s = sb + stage * SSTR;
        uint32_t bbase_s = abase_s + 2 * APLANE;
#pragma unroll
        for (int ks = 0; ks < 4; ks++) {
            uint32_t bfr[2][WNF][2];
#pragma unroll
            for (int p = 0; p < 2; p++)
#pragma unroll
                for (int nf = 0; nf < WNF; nf++) {
                    int r = warpN * WN + nf * 8 + (lane & 7);
                    int ck = ks * 2 + ((lane >> 3) & 1);
                    ldsm_x2(bfr[p][nf], bbase_s + p * BPLANE + swz(r, ck));
                }
#pragma unroll
            for (int p = 0; p < 2; p++) {
                uint32_t af[4][4];
#pragma unroll
                for (int mf = 0; mf < 4; mf++) {
                    int r = warpM * 64 + mf * 16 + (lane & 15);
                    int ck = ks * 2 + (lane >> 4);
                    ldsm_x4(af[mf], abase_s + p * APLANE + swz(r, ck));
                }
                int nq = 2 - p;
#pragma unroll
                for (int q = 0; q < 2; q++) {
                    if (q >= nq) break;
#pragma unroll
                    for (int mf = 0; mf < 4; mf++)
#pragma unroll
                        for (int nf = 0; nf < WNF; nf++)
                            mma_f16(acc[mf][nf], af[mf], bfr[q][nf]);
                }
            }
        }
        __syncthreads();
        stage ^= 1;
    }

    float* ssum = (float*)smem;
    float* ssq  = ((float*)smem) + 1024;
    int slot = warpM * 8 + (lane >> 2);
#pragma unroll
    for (int nf = 0; nf < WNF; nf++)
#pragma unroll
        for (int col = 0; col < 2; col++) {
            int oc = warpN * WN + nf * 8 + (lane & 3) * 2 + col;
            float s = 0.f, q = 0.f;
#pragma unroll
            for (int mf = 0; mf < 4; mf++) {
                float v0 = acc[mf][nf][col];
                float v1 = acc[mf][nf][col + 2];
                s += v0 + v1;
                q += v0 * v0 + v1 * v1;
            }
            ssum[oc * 16 + slot] = s;
            ssq[oc * 16 + slot] = q;
        }
    __syncthreads();
    if (t < 64) {
        float s = 0.f, q = 0.f;
#pragma unroll
        for (int i = 0; i < 16; i++) { s += ssum[t * 16 + i]; q += ssq[t * 16 + i]; }
        size_t pi = (size_t)(ocBase + t) * 2048 + blockIdx.x;
        g_bnpS[pi] = s; g_bnpQ[pi] = q;
    }

    const size_t cs = (size_t)1 << hwShift;
#pragma unroll
    for (int mf = 0; mf < 4; mf++)
#pragma unroll
        for (int nf = 0; nf < WNF; nf++) {
            int m0 = warpM * 64 + mf * 16 + (lane >> 2);
            int n0 = warpN * WN + nf * 8 + (lane & 3) * 2;
            float* base = raw + (((size_t)bImg * Cout + ocBase + n0) << hwShift) + pbase;
            base[m0] = acc[mf][nf][0];
            base[cs + m0] = acc[mf][nf][1];
            base[m0 + 8] = acc[mf][nf][2];
            base[cs + m0 + 8] = acc[mf][nf][3];
        }
}

// ------------------ head: offsets -> scatter -> fused body+cls --------------
__global__ void offsets_kernel()
{
    if (threadIdx.x == 0) {
        int s = 0;
        for (int e = 0; e < 12; e++) { g_off[e] = s; g_fill[e] = s; s += g_cnt[e]; }
    }
}
__global__ void scatter_kernel()
{
    int tkn = blockIdx.x * 256 + threadIdx.x;
    if (tkn >= 32768) return;
    int slot = atomicAdd(&g_fill[g_eidx[tkn]], 1);
    g_list[slot] = tkn;
}

// fused body GEMM + classifier
__global__ __launch_bounds__(512) void body_cls_kernel(
    const float* __restrict__ tok, const float* __restrict__ bw,
    const float* __restrict__ bb, const float* __restrict__ ow,
    const float* __restrict__ w1, const float* __restrict__ b1,
    const float* __restrict__ w2, const float* __restrict__ b2,
    float* __restrict__ out)
{
    extern __shared__ float dsm[];                 // 128*257 floats
    __shared__ int stok[128];
    float* As = dsm;
    float* Bs = dsm + 1056;
    int e = blockIdx.y;
    int nt = g_cnt[e];
    int m0 = blockIdx.x * 128;
    if (m0 >= nt) return;
    int t = threadIdx.x;
    if (t < 128) {
        int idx = m0 + t;
        stok[t] = g_list[g_off[e] + (idx < nt ? idx : 0)];
    }
    __syncthreads();
    int tx = t & 15, ty = t >> 4;
    float acc[8][8];
#pragma unroll
    for (int i = 0; i < 8; i++)
#pragma unroll
        for (int j = 0; j < 8; j++) acc[i][j] = 0.f;

    for (int k0 = 0; k0 < 256; k0 += 8) {
        for (int i = t; i < 1024; i += 512) {
            int kk = i & 7, m = i >> 3;
            As[kk * 132 + m] = tok[(size_t)stok[m] * 256 + k0 + kk];
        }
        for (int i = t; i < 2048; i += 512) {
            int kk = i >> 8, n = i & 255;
            Bs[kk * 256 + n] = bw[(size_t)(k0 + kk) * 3072 + e * 256 + n];
        }
        __syncthreads();
#pragma unroll
        for (int kk = 0; kk < 8; kk++) {
            float a[8], b[8];
#pragma unroll
            for (int i = 0; i < 8; i++) a[i] = As[kk * 132 + tx * 8 + i];
#pragma unroll
            for (int j = 0; j < 8; j++) b[j] = Bs[kk * 256 + ty * 8 + j];
#pragma unroll
            for (int i = 0; i < 8; i++)
#pragma unroll
                for (int j = 0; j < 8; j++) acc[i][j] = fmaf(a[i], b[j], acc[i][j]);
        }
        __syncthreads();
    }
#pragma unroll
    for (int i = 0; i < 8; i++) {
        int m = tx * 8 + i;
#pragma unroll
        for (int j = 0; j < 8; j++) {
            int n = ty * 8 + j, col = e * 256 + n;
            float v = acc[i][j] + bb[col];
            v = lrelu(v);
            v = lrelu(v * ow[col]);
            dsm[m * 257 + n] = v;
        }
    }
    __syncthreads();

    int wrp = t >> 5, lane = t & 31;
    for (int m = wrp; m < 128; m += 16) {
        if (m0 + m >= nt) continue;
        float h = b1[lane];
        const float* fr = dsm + m * 257;
#pragma unroll 8
        for (int d = 0; d < 256; d++) h = fmaf(fr[d], __ldg(w1 + d * 32 + lane), h);
        h = lrelu(h) * w2[lane];
#pragma unroll
        for (int o = 16; o > 0; o >>= 1) h += __shfl_xor_sync(0xffffffffu, h, o);
        if (lane == 0) out[stok[m]] = h + b2[0];
    }
}

// ------------------ launch --------------------------------------------------
extern "C" void kernel_launch(void* const* d_in, const int* in_sizes, int n_in,
                              void* d_out, int out_size)
{
    const float* x = (const float*)d_in[0];
    const float* c0w = (const float*)d_in[1];  const float* c0b = (const float*)d_in[2];
    const float* c1w = (const float*)d_in[3];  const float* g1 = (const float*)d_in[4];  const float* b1 = (const float*)d_in[5];
    const float* c2w = (const float*)d_in[6];  const float* g2 = (const float*)d_in[7];  const float* b2 = (const float*)d_in[8];
    const float* c3w = (const float*)d_in[9];  const float* g3 = (const float*)d_in[10]; const float* b3 = (const float*)d_in[11];
    const float* c4w = (const float*)d_in[12]; const float* g4 = (const float*)d_in[13]; const float* b4 = (const float*)d_in[14];
    const float* c5w = (const float*)d_in[15]; const float* g5 = (const float*)d_in[16]; const float* b5 = (const float*)d_in[17];
    const float* c6w = (const float*)d_in[18]; const float* g6 = (const float*)d_in[19]; const float* b6 = (const float*)d_in[20];
    const float* wg = (const float*)d_in[21];
    const float* bw = (const float*)d_in[22]; const float* bb = (const float*)d_in[23];
    const float* ow = (const float*)d_in[24];
    const float* cw1 = (const float*)d_in[25]; const float* cb1 = (const float*)d_in[26];
    const float* cw2 = (const float*)d_in[27]; const float* cb2 = (const float*)d_in[28];
    float* out = (float*)d_out;

    float *raw, *tok;
    __half *A0, *A1, *B0, *B1, *w0, *w1;
    cudaGetSymbolAddress((void**)&raw, g_raw);
    cudaGetSymbolAddress((void**)&tok, g_tok);
    cudaGetSymbolAddress((void**)&A0, g_A0); cudaGetSymbolAddress((void**)&A1, g_A1);
    cudaGetSymbolAddress((void**)&B0, g_B0); cudaGetSymbolAddress((void**)&B1, g_B1);
    cudaGetSymbolAddress((void**)&w0, g_w0); cudaGetSymbolAddress((void**)&w1, g_w1);

    const int O1 = 0, O2 = 65536, O3 = 139264, O4 = 401408, O5 = 696320, O6 = 1286144;

    const int SM64 = 2 * (2 * 16384 + 2 * 64 * 128);   // 98304
    cudaFuncSetAttribute(conv_mma, cudaFuncAttributeMaxDynamicSharedMemorySize, SM64);
    const int SMBC = 128 * 257 * 4;                    // 131584
    cudaFuncSetAttribute(body_cls_kernel, cudaFuncAttributeMaxDynamicSharedMemorySize, SMBC);

    wsplit_all_kernel<<<(1875968 + 255) / 256, 256>>>(c1w, c2w, c3w, c4w, c5w, c6w);
    conv0prep_kernel<<<dim3(2048, 8), 256>>>(x, c0w, c0b, A0, A1);

    // conv1: 64->64 4x4 s2
    conv_mma<<<dim3(1024, 1), 256, SM64>>>(A0, A1, w0 + O1, w1 + O1, raw,
        6, 4, 2, 256, 256, 14, 7, 64, 1024, 16);
    bnfin_kernel<<<64, 256>>>(g1, b1, 1024, 1.f / 131072.f);
    prep_kernel<<<dim3(8 * 128, 4), 256, 32 * 65 * 4>>>(raw, B0, B1, 64, 6, 128, 128);

    // conv2: 64->128 3x3 s1
    conv_mma<<<dim3(1024, 2), 256, SM64>>>(B0, B1, w0 + O2, w1 + O2, raw,
        6, 3, 1, 128, 128, 14, 7, 128, 576, 9);
    bnfin_kernel<<<128, 256>>>(g2, b2, 1024, 1.f / 131072.f);
    prep_kernel<<<dim3(8 * 128, 4), 256, 32 * 129 * 4>>>(raw, A0, A1, 128, 7, 128, 128);

    // conv3: 128->128 4x4 s2
    conv_mma<<<dim3(256, 2), 256, SM64>>>(A0, A1, w0 + O3, w1 + O3, raw,
        7, 4, 2, 128, 128, 12, 6, 128, 2048, 32);
    bnfin_kernel<<<128, 256>>>(g3, b3, 256, 1.f / 32768.f);
    prep_kernel<<<dim3(8 * 64, 2), 256, 32 * 129 * 4>>>(raw, B0, B1, 128, 7, 64, 64);

    // conv4: 128->256 3x3 s1
    conv_mma<<<dim3(256, 4), 256, SM64>>>(B0, B1, w0 + O4, w1 + O4, raw,
        7, 3, 1, 64, 64, 12, 6, 256, 1152, 18);
    bnfin_kernel<<<256, 256>>>(g4, b4, 256, 1.f / 32768.f);
    prep_kernel<<<dim3(8 * 64, 2), 256, 32 * 257 * 4>>>(raw, A0, A1, 256, 8, 64, 64);

    // conv5: 256->256 3x3 s1
    conv_mma<<<dim3(256, 4), 256, SM64>>>(A0, A1, w0 + O5, w1 + O5, raw,
        8, 3, 1, 64, 64, 12, 6, 256, 2304, 36);
    bnfin_kernel<<<256, 256>>>(g5, b5, 256, 1.f / 32768.f);
    prep_kernel<<<dim3(8 * 64, 2), 256, 32 * 257 * 4>>>(raw, B0, B1, 256, 8, 64, 64);

    // conv6: 256->256 3x3 s1
    conv_mma<<<dim3(256, 4), 256, SM64>>>(B0, B1, w0 + O6, w1 + O6, raw,
        8, 3, 1, 64, 64, 12, 6, 256, 2304, 36);
    bnfin_kernel<<<256, 256>>>(g6, b6, 256, 1.f / 32768.f);
    // prep_tok with fused router (deletes router_kernel + 32MB re-read)
    prep_tok_kernel<<<dim3(8 * 64, 2), 256, 32 * 257 * 4>>>(raw, tok, wg, 256, 8, 64, 64);

    // head
    offsets_kernel<<<1, 32>>>();
    scatter_kernel<<<128, 256>>>();
    body_cls_kernel<<<dim3(256, 12), 512, SMBC>>>(tok, bw, bb, ow,
                                                  cw1, cb1, cw2, cb2, out);
}

// round 17
// speedup vs baseline: 1.0457x; 1.0237x over previous
#include <cuda_runtime.h>
#include <cuda_fp16.h>
#include <cstdint>

// ------------------ static scratch ------------------------------------------
__device__ __align__(256) float  g_raw[33554432];          // raw conv out
__device__ __align__(256) __half g_A0[33554432], g_A1[33554432];
__device__ __align__(256) __half g_B0[8388608],  g_B1[8388608];
__device__ __align__(256) __half g_w0[2097152],  g_w1[2097152];   // all-layer arena
__device__ __align__(256) float  g_tok[8388608];
__device__ __align__(256) float  g_bnpS[524288], g_bnpQ[524288];  // [oc][tile<=2048]
__device__ float g_scale[256], g_shift[256];
__device__ int g_eidx[32768], g_list[32768];
__device__ int g_cnt[12], g_off[12], g_fill[12];

__device__ __forceinline__ float lrelu(float v) { return v >= 0.f ? v : 0.2f * v; }

// ------------------ asm helpers ---------------------------------------------
__device__ __forceinline__ uint32_t smem_u32(const void* p) {
    uint32_t a;
    asm("{ .reg .u64 t; cvta.to.shared.u64 t, %1; cvt.u32.u64 %0, t; }" : "=r"(a) : "l"(p));
    return a;
}
__device__ __forceinline__ void cp16(uint32_t dst, const void* src, int srcsize) {
    asm volatile("cp.async.cg.shared.global [%0], [%1], 16, %2;"
                 :: "r"(dst), "l"(src), "r"(srcsize) : "memory");
}
#define CP_COMMIT() asm volatile("cp.async.commit_group;" ::: "memory")
#define CP_WAIT1()  asm volatile("cp.async.wait_group 1;" ::: "memory")
#define CP_WAIT0()  asm volatile("cp.async.wait_group 0;" ::: "memory")

__device__ __forceinline__ void ldsm_x4(uint32_t* r, uint32_t a) {
    asm volatile("ldmatrix.sync.aligned.m8n8.x4.shared.b16 {%0,%1,%2,%3}, [%4];"
                 : "=r"(r[0]), "=r"(r[1]), "=r"(r[2]), "=r"(r[3]) : "r"(a));
}
__device__ __forceinline__ void ldsm_x2(uint32_t* r, uint32_t a) {
    asm volatile("ldmatrix.sync.aligned.m8n8.x2.shared.b16 {%0,%1}, [%2];"
                 : "=r"(r[0]), "=r"(r[1]) : "r"(a));
}
__device__ __forceinline__ void mma_f16(float* c, const uint32_t* a, const uint32_t* b) {
    asm volatile("mma.sync.aligned.m16n8k16.row.col.f32.f16.f16.f32 "
                 "{%0,%1,%2,%3}, {%4,%5,%6,%7}, {%8,%9}, {%0,%1,%2,%3};"
                 : "+f"(c[0]), "+f"(c[1]), "+f"(c[2]), "+f"(c[3])
                 : "r"(a[0]), "r"(a[1]), "r"(a[2]), "r"(a[3]), "r"(b[0]), "r"(b[1]));
}
__device__ __forceinline__ uint32_t swz(int row, int ck) {
    return (uint32_t)(row * 128 + ((ck ^ (row & 7)) * 16));
}

// ------- conv0+prep fused: 3->64 3x3 s1 p1 + bias + lrelu + split -> NHWC ---
__global__ __launch_bounds__(256) void conv0prep_kernel(
    const float* __restrict__ x, const float* __restrict__ w,
    const float* __restrict__ bias,
    __half* __restrict__ o0, __half* __restrict__ o1)
{
    __shared__ float ws[1792];
    __shared__ float ins[3][3][36];
    int by = blockIdx.x;
    int b = by >> 8, y = by & 255;
    int x0 = blockIdx.y * 32;
    int t = threadIdx.x;
    for (int i = t; i < 1728; i += 256) ws[i] = w[i];
    if (t < 64) ws[1728 + t] = bias[t];
    for (int i = t; i < 306; i += 256) {
        int c = i / 102, rr = i - c * 102;
        int ky = rr / 34, xx = rr - ky * 34;
        int iy = y + ky - 1, ix = x0 + xx - 1;
        float v = 0.f;
        if ((unsigned)iy < 256u && (unsigned)ix < 256u)
            v = x[((b * 3 + c) * 256 + iy) * 256 + ix];
        ins[c][ky][xx] = v;
    }
    __syncthreads();
    int px = t >> 3, og = t & 7;
    float acc[8];
#pragma unroll
    for (int j = 0; j < 8; j++) acc[j] = ws[1728 + og * 8 + j];
#pragma unroll
    for (int c = 0; c < 3; c++)
#pragma unroll
        for (int ky = 0; ky < 3; ky++)
#pragma unroll
            for (int kx = 0; kx < 3; kx++) {
                float iv = ins[c][ky][px + kx];
                int k = c * 9 + ky * 3 + kx;
#pragma unroll
                for (int j = 0; j < 8; j++)
                    acc[j] = fmaf(iv, ws[(og * 8 + j) * 27 + k], acc[j]);
            }
    size_t base = ((size_t)(b * 256 + y) * 256 + x0 + px) * 64 + og * 8;
    __half h0[8], h1[8];
#pragma unroll
    for (int j = 0; j < 8; j++) {
        float v = lrelu(acc[j]);
        h0[j] = __float2half_rn(v);
        h1[j] = __float2half_rn(v - __half2float(h0[j]));
    }
    *(uint4*)(o0 + base) = *(uint4*)h0;
    *(uint4*)(o1 + base) = *(uint4*)h1;
}

// ---- BN finalize ------------------------------------------------------------
__global__ void bnfin_kernel(const float* __restrict__ g, const float* __restrict__ bt,
                             int gx, float inv_n)
{
    int c = blockIdx.x, t = threadIdx.x;
    float s = 0.f, q = 0.f;
    for (int i = t; i < gx; i += 256) {
        s += g_bnpS[(size_t)c * 2048 + i];
        q += g_bnpQ[(size_t)c * 2048 + i];
    }
    __shared__ float ss[256], qq[256];
    ss[t] = s; qq[t] = q; __syncthreads();
    for (int o = 128; o > 0; o >>= 1) {
        if (t < o) { ss[t] += ss[t + o]; qq[t] += qq[t + o]; }
        __syncthreads();
    }
    if (t == 0) {
        float m = ss[0] * inv_n;
        float is = rsqrtf(qq[0] * inv_n - m * m + 1e-5f);
        float sc = g[c] * is;
        g_scale[c] = sc; g_shift[c] = bt[c] - m * sc;
    }
}

// ---- prep: bn+lrelu + NCHW->NHWC + 2-way fp16 split (vectorized) -----------
__global__ void prep_kernel(const float* __restrict__ raw,
                            __half* __restrict__ o0, __half* __restrict__ o1,
                            int C, int cShift, int H, int W)
{
    extern __shared__ float sp[];
    int by = blockIdx.x, b = by / H, y = by - b * H;
    int x0 = blockIdx.y * 32, t = threadIdx.x, st = C + 1;
    // load: float4 along x
    for (int i = t; i < C * 8; i += 256) {
        int c = i >> 3, xq = (i & 7) * 4;
        float4 v = *(const float4*)(raw + ((size_t)(b * C + c) * H + y) * W + x0 + xq);
        float sc = g_scale[c], sh = g_shift[c];
        sp[(xq + 0) * st + c] = lrelu(fmaf(v.x, sc, sh));
        sp[(xq + 1) * st + c] = lrelu(fmaf(v.y, sc, sh));
        sp[(xq + 2) * st + c] = lrelu(fmaf(v.z, sc, sh));
        sp[(xq + 3) * st + c] = lrelu(fmaf(v.w, sc, sh));
    }
    __syncthreads();
    // store: uint2 (4 halves) per plane
    int cq4 = cShift - 2, cm4 = (C >> 2) - 1;
    for (int i = t; i < C * 8; i += 256) {
        int x = i >> cq4, cq = (i & cm4) << 2;
        const float* sr = sp + x * st + cq;
        __half h[4], r[4];
#pragma unroll
        for (int k = 0; k < 4; k++) {
            float v = sr[k];
            h[k] = __float2half_rn(v);
            r[k] = __float2half_rn(v - __half2float(h[k]));
        }
        size_t dst = ((size_t)(b * H + y) * W + x0 + x) * C + cq;
        *(uint2*)(o0 + dst) = *(uint2*)h;
        *(uint2*)(o1 + dst) = *(uint2*)r;
    }
}

// ---- prep_tok + fused router (vectorized stores) ----------------------------
__global__ void prep_tok_kernel(const float* __restrict__ raw, float* __restrict__ tok,
                                const float* __restrict__ wg,
                                int C, int cShift, int H, int W)
{
    extern __shared__ float sp[];
    int by = blockIdx.x, b = by / H, y = by - b * H;
    int x0 = blockIdx.y * 32, t = threadIdx.x, st = C + 1;
    for (int i = t; i < C * 8; i += 256) {
        int c = i >> 3, xq = (i & 7) * 4;
        float4 v = *(const float4*)(raw + ((size_t)(b * C + c) * H + y) * W + x0 + xq);
        float sc = g_scale[c], sh = g_shift[c];
        sp[(xq + 0) * st + c] = lrelu(fmaf(v.x, sc, sh));
        sp[(xq + 1) * st + c] = lrelu(fmaf(v.y, sc, sh));
        sp[(xq + 2) * st + c] = lrelu(fmaf(v.z, sc, sh));
        sp[(xq + 3) * st + c] = lrelu(fmaf(v.w, sc, sh));
    }
    __syncthreads();
    int cq4 = cShift - 2, cm4 = (C >> 2) - 1;
    for (int i = t; i < C * 8; i += 256) {
        int x = i >> cq4, cq = (i & cm4) << 2;
        const float* sr = sp + x * st + cq;
        float4 v = make_float4(sr[0], sr[1], sr[2], sr[3]);
        *(float4*)(tok + ((size_t)(b * H + y) * W + x0 + x) * C + cq) = v;
    }
    // fused router (identical accumulation order to standalone router)
    int wrp = t >> 5, lane = t & 31;
#pragma unroll
    for (int xi = 0; xi < 4; xi++) {
        int x = wrp * 4 + xi;
        float l[12];
#pragma unroll
        for (int e = 0; e < 12; e++) l[e] = 0.f;
#pragma unroll
        for (int i = 0; i < 8; i++) {
            int d = lane + 32 * i;
            float tv = sp[x * st + d];
            const float* w = wg + d * 12;
#pragma unroll
            for (int e = 0; e < 12; e++) l[e] = fmaf(tv, __ldg(w + e), l[e]);
        }
#pragma unroll
        for (int e = 0; e < 12; e++)
#pragma unroll
            for (int o = 16; o > 0; o >>= 1) l[e] += __shfl_xor_sync(0xffffffffu, l[e], o);
        if (lane == 0) {
            int best = 0; float bv = l[0];
#pragma unroll
            for (int e = 1; e < 12; e++) if (l[e] > bv) { bv = l[e]; best = e; }
            int token = (b * H + y) * W + x0 + x;
            g_eidx[token] = best;
            atomicAdd(&g_cnt[best], 1);
        }
    }
}

// ---- wsplit_all: all 6 layers in one launch, + zero router counters --------
__global__ void wsplit_all_kernel(
    const float* __restrict__ w1p, const float* __restrict__ w2p,
    const float* __restrict__ w3p, const float* __restrict__ w4p,
    const float* __restrict__ w5p, const float* __restrict__ w6p)
{
    int idx = blockIdx.x * 256 + threadIdx.x;
    if (idx < 12) g_cnt[idx] = 0;
    const int ends[6] = {65536, 139264, 401408, 696320, 1286144, 1875968};
    if (idx >= 1875968) return;
    int L = 0;
#pragma unroll
    for (int i = 0; i < 6; i++) if (idx >= ends[i]) L = i + 1;
    int start = L == 0 ? 0 : ends[L - 1];
    int li = idx - start;
    const float* wp;
    int Cin, KW;
    switch (L) {
        case 0: wp = w1p; Cin = 64;  KW = 4; break;
        case 1: wp = w2p; Cin = 64;  KW = 3; break;
        case 2: wp = w3p; Cin = 128; KW = 4; break;
        case 3: wp = w4p; Cin = 128; KW = 3; break;
        case 4: wp = w5p; Cin = 256; KW = 3; break;
        default: wp = w6p; Cin = 256; KW = 3; break;
    }
    int K = KW * KW * Cin;
    int oc = li / K, k = li - oc * K;
    int tap = k / Cin, c = k - tap * Cin;
    int ky = tap / KW, kx = tap - ky * KW;
    float v = wp[((oc * Cin + c) * KW + ky) * KW + kx];
    __half h0 = __float2half_rn(v);
    float r1 = v - __half2float(h0);
    g_w0[idx] = h0; g_w1[idx] = __float2half_rn(r1);
}

// ------------------ mma.sync fp16 implicit-GEMM conv (R8 verbatim) ----------
__global__ __launch_bounds__(256, 2) void conv_mma(
    const __half* __restrict__ a0, const __half* __restrict__ a1,
    const __half* __restrict__ w0, const __half* __restrict__ w1,
    float* __restrict__ raw,
    int cinShift, int KW, int stride, int Hin, int Win,
    int hwShift, int wShift, int Cout, int K, int nChunk)
{
    extern __shared__ char smem[];
    constexpr int NBLK = 64;
    constexpr int APLANE = 16384;
    constexpr int BPLANE = NBLK * 128;
    constexpr int SSTR = 2 * APLANE + 2 * BPLANE;
    constexpr int WN = NBLK / 4, WNF = WN / 8;

    const uint32_t sb = smem_u32(smem);
    const int t = threadIdx.x, lane = t & 31, wrp = t >> 5;
    const int warpM = wrp >> 2, warpN = wrp & 3;
    const int tileP = blockIdx.x * 128, ocBase = blockIdx.y * NBLK;
    const int bImg = tileP >> hwShift;
    const int pbase = tileP - (bImg << hwShift);
    const int Cin = 1 << cinShift;

    const int arow = t >> 3, ack = t & 7;
    int ry[4], rx[4], abase[4];
    uint32_t asw[4];
#pragma unroll
    for (int j = 0; j < 4; j++) {
        int row = arow + 32 * j;
        int p = tileP + row;
        int b = p >> hwShift, pp = p - (b << hwShift);
        int oy = pp >> wShift, ox = pp - (oy << wShift);
        ry[j] = oy * stride - 1; rx[j] = ox * stride - 1;
        abase[j] = ((b * Hin + ry[j]) * Win + rx[j]) * Cin + ack * 8;
        asw[j] = swz(row, ack);
    }
    int bbase[2]; uint32_t bsw[2];
#pragma unroll
    for (int j = 0; j < 2; j++) {
        int row = arow + 32 * j;
        bbase[j] = (ocBase + row) * K + ack * 8;
        bsw[j] = swz(row, ack);
    }

    float acc[4][WNF][4];
#pragma unroll
    for (int i = 0; i < 4; i++)
#pragma unroll
        for (int j = 0; j < WNF; j++)
#pragma unroll
            for (int k = 0; k < 4; k++) acc[i][j][k] = 0.f;

    auto load_chunk = [&](int ch, int stage) {
        int k0 = ch * 64;
        int tap = k0 >> cinShift, c0 = k0 - (tap << cinShift);
        int ky = tap / KW, kx = tap - ky * KW;
        int delta = (ky * Win + kx) * Cin + c0;
        uint32_t sbase = sb + stage * SSTR;
#pragma unroll
        for (int j = 0; j < 4; j++) {
            int iy = ry[j] + ky, ix = rx[j] + kx;
            bool ok = ((unsigned)iy < (unsigned)Hin) && ((unsigned)ix < (unsigned)Win);
            int off = abase[j] + delta;
            cp16(sbase + asw[j], ok ? (const void*)(a0 + off) : (const void*)a0, ok ? 16 : 0);
            cp16(sbase + APLANE + asw[j], ok ? (const void*)(a1 + off) : (const void*)a1, ok ? 16 : 0);
        }
#pragma unroll
        for (int j = 0; j < 2; j++) {
            int off = bbase[j] + k0;
            cp16(sbase + 2 * APLANE + bsw[j], w0 + off, 16);
            cp16(sbase + 2 * APLANE + BPLANE + bsw[j], w1 + off, 16);
        }
    };

    load_chunk(0, 0);
    CP_COMMIT();

    int stage = 0;
#pragma unroll 1
    for (int ch = 0; ch < nChunk; ch++) {
        if (ch + 1 < nChunk) {
            load_chunk(ch + 1, stage ^ 1);
            CP_COMMIT();
            CP_WAIT1();
        } else {
            CP_WAIT0();
        }
        __syncthreads();

        uint32_t abase_s = sb + stage * SSTR;
        uint32_t bbase_s = abase_s + 2 * APLANE;
#pragma unroll
        for (int ks = 0; ks < 4; ks++) {
            uint32_t bfr[2][WNF][2];
#pragma unroll
            for (int p = 0; p < 2; p++)
#pragma unroll
                for (int nf = 0; nf < WNF; nf++) {
                    int r = warpN * WN + nf * 8 + (lane & 7);
                    int ck = ks * 2 + ((lane >> 3) & 1);
                    ldsm_x2(bfr[p][nf], bbase_s + p * BPLANE + swz(r, ck));
                }
#pragma unroll
            for (int p = 0; p < 2; p++) {
                uint32_t af[4][4];
#pragma unroll
                for (int mf = 0; mf < 4; mf++) {
                    int r = warpM * 64 + mf * 16 + (lane & 15);
                    int ck = ks * 2 + (lane >> 4);
                    ldsm_x4(af[mf], abase_s + p * APLANE + swz(r, ck));
                }
                int nq = 2 - p;
#pragma unroll
                for (int q = 0; q < 2; q++) {
                    if (q >= nq) break;
#pragma unroll
                    for (int mf = 0; mf < 4; mf++)
#pragma unroll
                        for (int nf = 0; nf < WNF; nf++)
                            mma_f16(acc[mf][nf], af[mf], bfr[q][nf]);
                }
            }
        }
        __syncthreads();
        stage ^= 1;
    }

    float* ssum = (float*)smem;
    float* ssq  = ((float*)smem) + 1024;
    int slot = warpM * 8 + (lane >> 2);
#pragma unroll
    for (int nf = 0; nf < WNF; nf++)
#pragma unroll
        for (int col = 0; col < 2; col++) {
            int oc = warpN * WN + nf * 8 + (lane & 3) * 2 + col;
            float s = 0.f, q = 0.f;
#pragma unroll
            for (int mf = 0; mf < 4; mf++) {
                float v0 = acc[mf][nf][col];
                float v1 = acc[mf][nf][col + 2];
                s += v0 + v1;
                q += v0 * v0 + v1 * v1;
            }
            ssum[oc * 16 + slot] = s;
            ssq[oc * 16 + slot] = q;
        }
    __syncthreads();
    if (t < 64) {
        float s = 0.f, q = 0.f;
#pragma unroll
        for (int i = 0; i < 16; i++) { s += ssum[t * 16 + i]; q += ssq[t * 16 + i]; }
        size_t pi = (size_t)(ocBase + t) * 2048 + blockIdx.x;
        g_bnpS[pi] = s; g_bnpQ[pi] = q;
    }

    const size_t cs = (size_t)1 << hwShift;
#pragma unroll
    for (int mf = 0; mf < 4; mf++)
#pragma unroll
        for (int nf = 0; nf < WNF; nf++) {
            int m0 = warpM * 64 + mf * 16 + (lane >> 2);
            int n0 = warpN * WN + nf * 8 + (lane & 3) * 2;
            float* base = raw + (((size_t)bImg * Cout + ocBase + n0) << hwShift) + pbase;
            base[m0] = acc[mf][nf][0];
            base[cs + m0] = acc[mf][nf][1];
            base[m0 + 8] = acc[mf][nf][2];
            base[cs + m0 + 8] = acc[mf][nf][3];
        }
}

// ------------------ head: offsets -> scatter -> fused body+cls --------------
__global__ void offsets_kernel()
{
    if (threadIdx.x == 0) {
        int s = 0;
        for (int e = 0; e < 12; e++) { g_off[e] = s; g_fill[e] = s; s += g_cnt[e]; }
    }
}
__global__ void scatter_kernel()
{
    int tkn = blockIdx.x * 256 + threadIdx.x;
    if (tkn >= 32768) return;
    int slot = atomicAdd(&g_fill[g_eidx[tkn]], 1);
    g_list[slot] = tkn;
}

// fused body GEMM + classifier
__global__ __launch_bounds__(512) void body_cls_kernel(
    const float* __restrict__ tok, const float* __restrict__ bw,
    const float* __restrict__ bb, const float* __restrict__ ow,
    const float* __restrict__ w1, const float* __restrict__ b1,
    const float* __restrict__ w2, const float* __restrict__ b2,
    float* __restrict__ out)
{
    extern __shared__ float dsm[];                 // 128*257 floats
    __shared__ int stok[128];
    float* As = dsm;
    float* Bs = dsm + 1056;
    int e = blockIdx.y;
    int nt = g_cnt[e];
    int m0 = blockIdx.x * 128;
    if (m0 >= nt) return;
    int t = threadIdx.x;
    if (t < 128) {
        int idx = m0 + t;
        stok[t] = g_list[g_off[e] + (idx < nt ? idx : 0)];
    }
    __syncthreads();
    int tx = t & 15, ty = t >> 4;
    float acc[8][8];
#pragma unroll
    for (int i = 0; i < 8; i++)
#pragma unroll
        for (int j = 0; j < 8; j++) acc[i][j] = 0.f;

    for (int k0 = 0; k0 < 256; k0 += 8) {
        for (int i = t; i < 1024; i += 512) {
            int kk = i & 7, m = i >> 3;
            As[kk * 132 + m] = tok[(size_t)stok[m] * 256 + k0 + kk];
        }
        for (int i = t; i < 2048; i += 512) {
            int kk = i >> 8, n = i & 255;
            Bs[kk * 256 + n] = bw[(size_t)(k0 + kk) * 3072 + e * 256 + n];
        }
        __syncthreads();
#pragma unroll
        for (int kk = 0; kk < 8; kk++) {
            float a[8], b[8];
#pragma unroll
            for (int i = 0; i < 8; i++) a[i] = As[kk * 132 + tx * 8 + i];
#pragma unroll
            for (int j = 0; j < 8; j++) b[j] = Bs[kk * 256 + ty * 8 + j];
#pragma unroll
            for (int i = 0; i < 8; i++)
#pragma unroll
                for (int j = 0; j < 8; j++) acc[i][j] = fmaf(a[i], b[j], acc[i][j]);
        }
        __syncthreads();
    }
#pragma unroll
    for (int i = 0; i < 8; i++) {
        int m = tx * 8 + i;
#pragma unroll
        for (int j = 0; j < 8; j++) {
            int n = ty * 8 + j, col = e * 256 + n;
            float v = acc[i][j] + bb[col];
            v = lrelu(v);
            v = lrelu(v * ow[col]);
            dsm[m * 257 + n] = v;
        }
    }
    __syncthreads();

    int wrp = t >> 5, lane = t & 31;
    for (int m = wrp; m < 128; m += 16) {
        if (m0 + m >= nt) continue;
        float h = b1[lane];
        const float* fr = dsm + m * 257;
#pragma unroll 8
        for (int d = 0; d < 256; d++) h = fmaf(fr[d], __ldg(w1 + d * 32 + lane), h);
        h = lrelu(h) * w2[lane];
#pragma unroll
        for (int o = 16; o > 0; o >>= 1) h += __shfl_xor_sync(0xffffffffu, h, o);
        if (lane == 0) out[stok[m]] = h + b2[0];
    }
}

// ------------------ launch --------------------------------------------------
extern "C" void kernel_launch(void* const* d_in, const int* in_sizes, int n_in,
                              void* d_out, int out_size)
{
    const float* x = (const float*)d_in[0];
    const float* c0w = (const float*)d_in[1];  const float* c0b = (const float*)d_in[2];
    const float* c1w = (const float*)d_in[3];  const float* g1 = (const float*)d_in[4];  const float* b1 = (const float*)d_in[5];
    const float* c2w = (const float*)d_in[6];  const float* g2 = (const float*)d_in[7];  const float* b2 = (const float*)d_in[8];
    const float* c3w = (const float*)d_in[9];  const float* g3 = (const float*)d_in[10]; const float* b3 = (const float*)d_in[11];
    const float* c4w = (const float*)d_in[12]; const float* g4 = (const float*)d_in[13]; const float* b4 = (const float*)d_in[14];
    const float* c5w = (const float*)d_in[15]; const float* g5 = (const float*)d_in[16]; const float* b5 = (const float*)d_in[17];
    const float* c6w = (const float*)d_in[18]; const float* g6 = (const float*)d_in[19]; const float* b6 = (const float*)d_in[20];
    const float* wg = (const float*)d_in[21];
    const float* bw = (const float*)d_in[22]; const float* bb = (const float*)d_in[23];
    const float* ow = (const float*)d_in[24];
    const float* cw1 = (const float*)d_in[25]; const float* cb1 = (const float*)d_in[26];
    const float* cw2 = (const float*)d_in[27]; const float* cb2 = (const float*)d_in[28];
    float* out = (float*)d_out;

    float *raw, *tok;
    __half *A0, *A1, *B0, *B1, *w0, *w1;
    cudaGetSymbolAddress((void**)&raw, g_raw);
    cudaGetSymbolAddress((void**)&tok, g_tok);
    cudaGetSymbolAddress((void**)&A0, g_A0); cudaGetSymbolAddress((void**)&A1, g_A1);
    cudaGetSymbolAddress((void**)&B0, g_B0); cudaGetSymbolAddress((void**)&B1, g_B1);
    cudaGetSymbolAddress((void**)&w0, g_w0); cudaGetSymbolAddress((void**)&w1, g_w1);

    const int O1 = 0, O2 = 65536, O3 = 139264, O4 = 401408, O5 = 696320, O6 = 1286144;

    const int SM64 = 2 * (2 * 16384 + 2 * 64 * 128);   // 98304
    cudaFuncSetAttribute(conv_mma, cudaFuncAttributeMaxDynamicSharedMemorySize, SM64);
    const int SMBC = 128 * 257 * 4;                    // 131584
    cudaFuncSetAttribute(body_cls_kernel, cudaFuncAttributeMaxDynamicSharedMemorySize, SMBC);

    wsplit_all_kernel<<<(1875968 + 255) / 256, 256>>>(c1w, c2w, c3w, c4w, c5w, c6w);
    conv0prep_kernel<<<dim3(2048, 8), 256>>>(x, c0w, c0b, A0, A1);

    // conv1: 64->64 4x4 s2
    conv_mma<<<dim3(1024, 1), 256, SM64>>>(A0, A1, w0 + O1, w1 + O1, raw,
        6, 4, 2, 256, 256, 14, 7, 64, 1024, 16);
    bnfin_kernel<<<64, 256>>>(g1, b1, 1024, 1.f / 131072.f);
    prep_kernel<<<dim3(8 * 128, 4), 256, 32 * 65 * 4>>>(raw, B0, B1, 64, 6, 128, 128);

    // conv2: 64->128 3x3 s1
    conv_mma<<<dim3(1024, 2), 256, SM64>>>(B0, B1, w0 + O2, w1 + O2, raw,
        6, 3, 1, 128, 128, 14, 7, 128, 576, 9);
    bnfin_kernel<<<128, 256>>>(g2, b2, 1024, 1.f / 131072.f);
    prep_kernel<<<dim3(8 * 128, 4), 256, 32 * 129 * 4>>>(raw, A0, A1, 128, 7, 128, 128);

    // conv3: 128->128 4x4 s2
    conv_mma<<<dim3(256, 2), 256, SM64>>>(A0, A1, w0 + O3, w1 + O3, raw,
        7, 4, 2, 128, 128, 12, 6, 128, 2048, 32);
    bnfin_kernel<<<128, 256>>>(g3, b3, 256, 1.f / 32768.f);
    prep_kernel<<<dim3(8 * 64, 2), 256, 32 * 129 * 4>>>(raw, B0, B1, 128, 7, 64, 64);

    // conv4: 128->256 3x3 s1
    conv_mma<<<dim3(256, 4), 256, SM64>>>(B0, B1, w0 + O4, w1 + O4, raw,
        7, 3, 1, 64, 64, 12, 6, 256, 1152, 18);
    bnfin_kernel<<<256, 256>>>(g4, b4, 256, 1.f / 32768.f);
    prep_kernel<<<dim3(8 * 64, 2), 256, 32 * 257 * 4>>>(raw, A0, A1, 256, 8, 64, 64);

    // conv5: 256->256 3x3 s1
    conv_mma<<<dim3(256, 4), 256, SM64>>>(A0, A1, w0 + O5, w1 + O5, raw,
        8, 3, 1, 64, 64, 12, 6, 256, 2304, 36);
    bnfin_kernel<<<256, 256>>>(g5, b5, 256, 1.f / 32768.f);
    prep_kernel<<<dim3(8 * 64, 2), 256, 32 * 257 * 4>>>(raw, B0, B1, 256, 8, 64, 64);

    // conv6: 256->256 3x3 s1
    conv_mma<<<dim3(256, 4), 256, SM64>>>(B0, B1, w0 + O6, w1 + O6, raw,
        8, 3, 1, 64, 64, 12, 6, 256, 2304, 36);
    bnfin_kernel<<<256, 256>>>(g6, b6, 256, 1.f / 32768.f);
    prep_tok_kernel<<<dim3(8 * 64, 2), 256, 32 * 257 * 4>>>(raw, tok, wg, 256, 8, 64, 64);

    // head
    offsets_kernel<<<1, 32>>>();
    scatter_kernel<<<128, 256>>>();
    body_cls_kernel<<<dim3(256, 12), 512, SMBC>>>(tok, bw, bb, ow,
                                                  cw1, cb1, cw2, cb2, out);
}